// round 1
// baseline (speedup 1.0000x reference)
#include <cuda_runtime.h>
#include <math.h>

#define BATCH 4
#define CHN   128
#define HDIM  176
#define WDIM  176
#define HW    30976            // 176*176
#define PTOT  123904           // BATCH*HW
#define NWIN  1936             // 44*44
#define PB    3964928ULL       // per-batch plane = 128*30976 = 2048*1936
#define SLOT  15859712ULL      // PTOT*128

// scratch slots:
// s0: Aq  -> later x1          s1: Akv -> later AO -> later y_in[0]
// s2: Q   s3: K   s4: V        s1..s8: y_in (P x 1024)
// s9..s12: y_g (P x 512)
__device__ float g_s[13ULL * SLOT];
__device__ float g_mu2[PTOT];
__device__ float g_rstd2[PTOT];

// ---------------------------------------------------------------------------
// K1: LN1(x), bilinear mask/edge upsample (x4, half-pixel, edge-renorm == clamp),
//     A_kv = LN1(x)*mask_r  (slot1),  A_q = edge_r (slot0). NHWC rows per pixel.
// ---------------------------------------------------------------------------
__global__ void __launch_bounds__(256) k_prep(
    const float* __restrict__ x, const float* __restrict__ mask,
    const float* __restrict__ edge, const float* __restrict__ ln1w,
    const float* __restrict__ ln1b)
{
    __shared__ float xs[128 * 33];
    __shared__ float red[264], red2[264];
    __shared__ float ms[32], mu_s[32], rs_s[32];
    __shared__ int   cy0[32], cy1[32], cx0[32], cx1[32];
    __shared__ float cwy[32], cwx[32];

    int p0 = blockIdx.x * 32;
    int b = p0 / HW, hw0 = p0 % HW;
    const float* xb = x + (size_t)b * PB;

    for (int e = threadIdx.x; e < 4096; e += 256) {
        int c = e >> 5, px = e & 31;
        xs[c * 33 + px] = xb[(size_t)c * HW + hw0 + px];
    }
    if (threadIdx.x < 32) {
        int px = threadIdx.x;
        int hw = hw0 + px;
        int h2 = hw / WDIM, w2 = hw % WDIM;
        float fy = 0.25f * h2 - 0.375f; int iy = (int)floorf(fy); float ty = fy - iy;
        float fx = 0.25f * w2 - 0.375f; int ix = (int)floorf(fx); float tx = fx - ix;
        int y0 = iy < 0 ? 0 : iy, y1 = (iy + 1 > 43) ? 43 : iy + 1;
        int x0 = ix < 0 ? 0 : ix, x1 = (ix + 1 > 43) ? 43 : ix + 1;
        cy0[px] = y0; cy1[px] = y1; cx0[px] = x0; cx1[px] = x1;
        cwy[px] = ty; cwx[px] = tx;
        const float* mb = mask + b * NWIN;
        ms[px] = (1.f - ty) * ((1.f - tx) * mb[y0 * 44 + x0] + tx * mb[y0 * 44 + x1])
               +        ty  * ((1.f - tx) * mb[y1 * 44 + x0] + tx * mb[y1 * 44 + x1]);
    }
    __syncthreads();
    {
        int px = threadIdx.x & 31, j = threadIdx.x >> 5;
        float s = 0.f, s2 = 0.f;
        #pragma unroll
        for (int i = 0; i < 16; i++) {
            float v = xs[(j * 16 + i) * 33 + px];
            s += v; s2 += v * v;
        }
        red[j * 33 + px] = s; red2[j * 33 + px] = s2;
    }
    __syncthreads();
    if (threadIdx.x < 32) {
        int px = threadIdx.x; float s = 0.f, s2 = 0.f;
        #pragma unroll
        for (int j = 0; j < 8; j++) { s += red[j * 33 + px]; s2 += red2[j * 33 + px]; }
        float mu = s * (1.f / 128.f);
        float var = s2 * (1.f / 128.f) - mu * mu;
        mu_s[px] = mu; rs_s[px] = rsqrtf(var + 1e-5f);
    }
    __syncthreads();
    float* Akv = g_s + SLOT;
    for (int e = threadIdx.x; e < 4096; e += 256) {
        int px = e >> 7, c = e & 127;
        float v = (xs[c * 33 + px] - mu_s[px]) * rs_s[px] * ln1w[c] + ln1b[c];
        Akv[(size_t)(p0 + px) * 128 + c] = v * ms[px];
    }
    __syncthreads();
    for (int e = threadIdx.x; e < 4096; e += 256) {
        int c = e >> 5, px = e & 31;
        const float* eb = edge + ((size_t)b * 128 + c) * NWIN;
        float ty = cwy[px], tx = cwx[px];
        float v = (1.f - ty) * ((1.f - tx) * eb[cy0[px] * 44 + cx0[px]] + tx * eb[cy0[px] * 44 + cx1[px]])
                +        ty  * ((1.f - tx) * eb[cy1[px] * 44 + cx0[px]] + tx * eb[cy1[px] * 44 + cx1[px]]);
        xs[c * 33 + px] = v;
    }
    __syncthreads();
    float* Aq = g_s;
    for (int e = threadIdx.x; e < 4096; e += 256) {
        int px = e >> 7, c = e & 127;
        Aq[(size_t)(p0 + px) * 128 + c] = xs[c * 33 + px];
    }
}

// ---------------------------------------------------------------------------
// Generic fp32 GEMM: C[m][n] = sum_k A[m][k] * Wt[n][k]
// A row-major (lda=Kd) taken from scratch slot; C row-major into scratch slot.
// BM=BN=128, BK=16, 256 threads, 8x8 per thread.
// ---------------------------------------------------------------------------
__global__ void __launch_bounds__(256) k_gemm_rm(
    int aslot, const float* __restrict__ Wt, int cslot, int Kd, int Nd)
{
    __shared__ float As[16 * 132];
    __shared__ float Bs[16 * 132];
    const float* A = g_s + (size_t)aslot * SLOT;
    float* Cc = g_s + (size_t)cslot * SLOT;
    int m0 = blockIdx.x * 128, n0 = blockIdx.y * 128;
    int tx = threadIdx.x & 15, ty = threadIdx.x >> 4;
    float acc[8][8];
    #pragma unroll
    for (int i = 0; i < 8; i++)
        #pragma unroll
        for (int j = 0; j < 8; j++) acc[i][j] = 0.f;

    for (int k0 = 0; k0 < Kd; k0 += 16) {
        #pragma unroll
        for (int i = 0; i < 8; i++) {
            int e = threadIdx.x + i * 256;
            int r = e >> 4, kk = e & 15;
            As[kk * 132 + r] = A[(size_t)(m0 + r) * Kd + k0 + kk];
            Bs[kk * 132 + r] = Wt[(size_t)(n0 + r) * Kd + k0 + kk];
        }
        __syncthreads();
        #pragma unroll
        for (int kk = 0; kk < 16; kk++) {
            float4 a0 = *(const float4*)(As + kk * 132 + ty * 8);
            float4 a1 = *(const float4*)(As + kk * 132 + ty * 8 + 4);
            float4 b0 = *(const float4*)(Bs + kk * 132 + tx * 8);
            float4 b1 = *(const float4*)(Bs + kk * 132 + tx * 8 + 4);
            float av[8] = {a0.x, a0.y, a0.z, a0.w, a1.x, a1.y, a1.z, a1.w};
            float bv[8] = {b0.x, b0.y, b0.z, b0.w, b1.x, b1.y, b1.z, b1.w};
            #pragma unroll
            for (int i = 0; i < 8; i++)
                #pragma unroll
                for (int j = 0; j < 8; j++) acc[i][j] += av[i] * bv[j];
        }
        __syncthreads();
    }
    #pragma unroll
    for (int i = 0; i < 8; i++) {
        size_t row = (size_t)(m0 + ty * 8 + i) * Nd + n0 + tx * 8;
        *(float4*)(Cc + row)     = make_float4(acc[i][0], acc[i][1], acc[i][2], acc[i][3]);
        *(float4*)(Cc + row + 4) = make_float4(acc[i][4], acc[i][5], acc[i][6], acc[i][7]);
    }
}

// ---------------------------------------------------------------------------
// K3: per-(window,token) channel attention. Writes AO in "merged" layout:
// AO[b][n*128+ch][ihw]  (per batch 2048x1936 == flat NCHW 128x30976).
// ---------------------------------------------------------------------------
__global__ void __launch_bounds__(256) k_attn()
{
    __shared__ float outs[32 * 129];
    __shared__ float buf[8 * 640];
    int bid = blockIdx.x;
    int chunk = bid % 61;
    int n = (bid / 61) % 16;
    int b = bid / (61 * 16);
    int ihw0 = chunk * 32;
    const float* Q  = g_s + 2 * SLOT;
    const float* Kp = g_s + 3 * SLOT;
    const float* V  = g_s + 4 * SLOT;
    float* AO = g_s + SLOT;
    int warp = threadIdx.x >> 5, lane = threadIdx.x & 31;
    float* qs = buf + warp * 640;
    float* ks = qs + 128;
    float* vs = qs + 256;
    float* ds = qs + 384;

    for (int it = 0; it < 4; it++) {
        int g = it * 8 + warp;
        int ihw = ihw0 + g;
        if (ihw < NWIN) {
            int ih = ihw / 44, iw = ihw % 44;
            int h2 = ih * 4 + (n >> 2), w2 = iw * 4 + (n & 3);
            size_t p = (size_t)b * HW + (size_t)h2 * 176 + w2;
            for (int i = lane; i < 128; i += 32) {
                qs[i] = Q[p * 128 + i];
                ks[i] = Kp[p * 128 + i];
                vs[i] = V[p * 128 + i];
            }
            __syncwarp();
            for (int e = lane; e < 256; e += 32) {
                int j = e >> 4, kk = e & 15;
                float s = 0.f;
                #pragma unroll
                for (int i = 0; i < 8; i++) s += qs[i * 16 + j] * ks[i * 16 + kk];
                ds[e] = s * 0.25f;
            }
            __syncwarp();
            if (lane < 16) {
                float mx = -1e30f;
                #pragma unroll
                for (int kk = 0; kk < 16; kk++) mx = fmaxf(mx, ds[lane * 16 + kk]);
                float sm = 0.f;
                #pragma unroll
                for (int kk = 0; kk < 16; kk++) {
                    float ev = __expf(ds[lane * 16 + kk] - mx);
                    ds[lane * 16 + kk] = ev; sm += ev;
                }
                float inv = 1.f / sm;
                #pragma unroll
                for (int kk = 0; kk < 16; kk++) ds[lane * 16 + kk] *= inv;
            }
            __syncwarp();
            for (int ch = lane; ch < 128; ch += 32) {
                int i = ch >> 4, j = ch & 15;
                float s = 0.f;
                #pragma unroll
                for (int kk = 0; kk < 16; kk++) s += ds[j * 16 + kk] * vs[i * 16 + kk];
                outs[g * 129 + ch] = s;
            }
        }
    }
    __syncthreads();
    size_t base = ((size_t)b * 2048 + (size_t)n * 128) * 1936 + ihw0;
    for (int e = threadIdx.x; e < 4096; e += 256) {
        int ch = e >> 5, g = e & 31;
        if (ihw0 + g < NWIN)
            AO[base + (size_t)ch * 1936 + g] = outs[g * 129 + ch];
    }
}

// ---------------------------------------------------------------------------
// K4: merged residual is a PURE elementwise add (layout identity!), plus LN2 stats.
// x1 (slot0, NCHW) = x + AO.  mu2/rstd2 per pixel.
// ---------------------------------------------------------------------------
__global__ void __launch_bounds__(256) k_merge(const float* __restrict__ x)
{
    __shared__ float red[264], red2[264];
    int p0 = blockIdx.x * 32;
    int b = p0 / HW, hw0 = p0 % HW;
    int px = threadIdx.x & 31, j = threadIdx.x >> 5;
    const float* AO = g_s + SLOT;
    float* x1 = g_s;
    size_t base = (size_t)b * PB + hw0 + px;
    float s = 0.f, s2 = 0.f;
    #pragma unroll
    for (int i = 0; i < 16; i++) {
        int c = j * 16 + i;
        size_t idx = base + (size_t)c * HW;
        float v = x[idx] + AO[idx];
        x1[idx] = v; s += v; s2 += v * v;
    }
    red[j * 33 + px] = s; red2[j * 33 + px] = s2;
    __syncthreads();
    if (threadIdx.x < 32) {
        float ss = 0.f, ss2 = 0.f;
        #pragma unroll
        for (int j2 = 0; j2 < 8; j2++) { ss += red[j2 * 33 + threadIdx.x]; ss2 += red2[j2 * 33 + threadIdx.x]; }
        float mu = ss * (1.f / 128.f);
        float var = ss2 * (1.f / 128.f) - mu * mu;
        g_mu2[p0 + threadIdx.x] = mu;
        g_rstd2[p0 + threadIdx.x] = rsqrtf(var + 1e-5f);
    }
}

// ---------------------------------------------------------------------------
// K5: conv_in GEMM. A = LN2(x1) read straight from NCHW (coalesced along hw),
// LN applied in the A-load. C = y_in [P][1024] at slot1.
// ---------------------------------------------------------------------------
__global__ void __launch_bounds__(256) k_gemm_in(
    const float* __restrict__ Wt, const float* __restrict__ ln2w,
    const float* __restrict__ ln2b)
{
    __shared__ float As[16 * 132];
    __shared__ float Bs[16 * 132];
    __shared__ float mus[128], rss[128];
    int m0 = blockIdx.x * 128, n0 = blockIdx.y * 128;
    int b = m0 / HW, hw0 = m0 % HW;
    const float* x1 = g_s;
    float* yin = g_s + SLOT;
    if (threadIdx.x < 128) {
        mus[threadIdx.x] = g_mu2[m0 + threadIdx.x];
        rss[threadIdx.x] = g_rstd2[m0 + threadIdx.x];
    }
    int tx = threadIdx.x & 15, ty = threadIdx.x >> 4;
    float acc[8][8];
    #pragma unroll
    for (int i = 0; i < 8; i++)
        #pragma unroll
        for (int j = 0; j < 8; j++) acc[i][j] = 0.f;
    __syncthreads();

    for (int k0 = 0; k0 < 128; k0 += 16) {
        #pragma unroll
        for (int i = 0; i < 8; i++) {
            int e = threadIdx.x + i * 256;
            int kk = e >> 7, r = e & 127;
            float raw = x1[((size_t)b * 128 + k0 + kk) * HW + hw0 + r];
            As[kk * 132 + r] = (raw - mus[r]) * rss[r] * ln2w[k0 + kk] + ln2b[k0 + kk];
        }
        #pragma unroll
        for (int i = 0; i < 8; i++) {
            int e = threadIdx.x + i * 256;
            int r = e >> 4, kk = e & 15;
            Bs[kk * 132 + r] = Wt[(size_t)(n0 + r) * 128 + k0 + kk];
        }
        __syncthreads();
        #pragma unroll
        for (int kk = 0; kk < 16; kk++) {
            float4 a0 = *(const float4*)(As + kk * 132 + ty * 8);
            float4 a1 = *(const float4*)(As + kk * 132 + ty * 8 + 4);
            float4 b0 = *(const float4*)(Bs + kk * 132 + tx * 8);
            float4 b1 = *(const float4*)(Bs + kk * 132 + tx * 8 + 4);
            float av[8] = {a0.x, a0.y, a0.z, a0.w, a1.x, a1.y, a1.z, a1.w};
            float bv[8] = {b0.x, b0.y, b0.z, b0.w, b1.x, b1.y, b1.z, b1.w};
            #pragma unroll
            for (int i = 0; i < 8; i++)
                #pragma unroll
                for (int j = 0; j < 8; j++) acc[i][j] += av[i] * bv[j];
        }
        __syncthreads();
    }
    #pragma unroll
    for (int i = 0; i < 8; i++) {
        size_t row = (size_t)(m0 + ty * 8 + i) * 1024 + n0 + tx * 8;
        *(float4*)(yin + row)     = make_float4(acc[i][0], acc[i][1], acc[i][2], acc[i][3]);
        *(float4*)(yin + row + 4) = make_float4(acc[i][4], acc[i][5], acc[i][6], acc[i][7]);
    }
}

// ---------------------------------------------------------------------------
// K6: depthwise 3x3 (pad 1) on y_in (NHWC, 1024 ch) + exact GELU gate.
// y_g[p][ch] = gelu(dw(y1))[ch] * dw(y2)[ch],  ch in [0,512).
// ---------------------------------------------------------------------------
__global__ void __launch_bounds__(256) k_dwconv(const float* __restrict__ wdw)
{
    int idx = blockIdx.x * 256 + threadIdx.x;
    int ch = idx & 511;
    int p = idx >> 9;
    int b = p / HW, hw = p % HW;
    int h = hw / 176, w = hw % 176;
    const float* yin = g_s + SLOT;
    float* yg = g_s + 9 * SLOT;
    float wa[9], wb[9];
    #pragma unroll
    for (int t = 0; t < 9; t++) {
        wa[t] = __ldg(&wdw[ch * 9 + t]);
        wb[t] = __ldg(&wdw[(ch + 512) * 9 + t]);
    }
    float a = 0.f, gg = 0.f;
    #pragma unroll
    for (int dy = -1; dy <= 1; dy++) {
        int hh = h + dy; if (hh < 0 || hh >= 176) continue;
        #pragma unroll
        for (int dx = -1; dx <= 1; dx++) {
            int ww2 = w + dx; if (ww2 < 0 || ww2 >= 176) continue;
            size_t q = ((size_t)b * HW + (size_t)hh * 176 + ww2) * 1024;
            int t = (dy + 1) * 3 + dx + 1;
            a  += yin[q + ch] * wa[t];
            gg += yin[q + 512 + ch] * wb[t];
        }
    }
    float ge = 0.5f * a * (1.f + erff(a * 0.70710678118654752f));
    yg[(size_t)p * 512 + ch] = ge * gg;
}

// ---------------------------------------------------------------------------
// K7: conv_out GEMM (K=512) + residual, writes final NCHW output.
// ---------------------------------------------------------------------------
__global__ void __launch_bounds__(256) k_gemm_out(
    const float* __restrict__ Wt, float* __restrict__ outp)
{
    __shared__ float As[16 * 132];
    __shared__ float Bs[16 * 132];
    int m0 = blockIdx.x * 128;
    const float* A = g_s + 9 * SLOT;   // y_g, [P][512]
    const float* x1 = g_s;             // NCHW
    int tx = threadIdx.x & 15, ty = threadIdx.x >> 4;
    float acc[8][8];
    #pragma unroll
    for (int i = 0; i < 8; i++)
        #pragma unroll
        for (int j = 0; j < 8; j++) acc[i][j] = 0.f;

    for (int k0 = 0; k0 < 512; k0 += 16) {
        #pragma unroll
        for (int i = 0; i < 8; i++) {
            int e = threadIdx.x + i * 256;
            int r = e >> 4, kk = e & 15;
            As[kk * 132 + r] = A[(size_t)(m0 + r) * 512 + k0 + kk];
            Bs[kk * 132 + r] = Wt[(size_t)r * 512 + k0 + kk];
        }
        __syncthreads();
        #pragma unroll
        for (int kk = 0; kk < 16; kk++) {
            float4 a0 = *(const float4*)(As + kk * 132 + ty * 8);
            float4 a1 = *(const float4*)(As + kk * 132 + ty * 8 + 4);
            float4 b0 = *(const float4*)(Bs + kk * 132 + tx * 8);
            float4 b1 = *(const float4*)(Bs + kk * 132 + tx * 8 + 4);
            float av[8] = {a0.x, a0.y, a0.z, a0.w, a1.x, a1.y, a1.z, a1.w};
            float bv[8] = {b0.x, b0.y, b0.z, b0.w, b1.x, b1.y, b1.z, b1.w};
            #pragma unroll
            for (int i = 0; i < 8; i++)
                #pragma unroll
                for (int j = 0; j < 8; j++) acc[i][j] += av[i] * bv[j];
        }
        __syncthreads();
    }
    int b = m0 / HW, hw0 = m0 % HW;
    #pragma unroll
    for (int j = 0; j < 8; j++) {
        int n = tx * 8 + j;
        size_t obase = ((size_t)b * 128 + n) * HW + hw0 + ty * 8;
        #pragma unroll
        for (int i = 0; i < 8; i++) {
            outp[obase + i] = x1[obase + i] + acc[i][j];
        }
    }
}

// ---------------------------------------------------------------------------
extern "C" void kernel_launch(void* const* d_in, const int* in_sizes, int n_in,
                              void* d_out, int out_size)
{
    const float* x    = (const float*)d_in[0];
    const float* mask = (const float*)d_in[1];
    const float* edge = (const float*)d_in[2];
    const float* ln1w = (const float*)d_in[3];
    const float* ln1b = (const float*)d_in[4];
    const float* Wq   = (const float*)d_in[5];
    const float* Wk   = (const float*)d_in[6];
    const float* Wv   = (const float*)d_in[7];
    const float* ln2w = (const float*)d_in[8];
    const float* ln2b = (const float*)d_in[9];
    const float* w_in = (const float*)d_in[10];
    const float* w_dw = (const float*)d_in[11];
    const float* w_out= (const float*)d_in[12];
    float* outp = (float*)d_out;

    // K1: LN1 + resize + window inputs (Aq slot0, Akv slot1)
    k_prep<<<PTOT / 32, 256>>>(x, mask, edge, ln1w, ln1b);

    // K2: Q/K/V GEMMs (M=123904, N=128, K=128)
    k_gemm_rm<<<dim3(PTOT / 128, 1), 256>>>(0, Wq, 2, 128, 128);
    k_gemm_rm<<<dim3(PTOT / 128, 1), 256>>>(1, Wk, 3, 128, 128);
    k_gemm_rm<<<dim3(PTOT / 128, 1), 256>>>(1, Wv, 4, 128, 128);

    // K3: channel attention -> AO (slot1, merged layout)
    k_attn<<<4 * 16 * 61, 256>>>();

    // K4: x1 = x + AO (elementwise!) + LN2 stats
    k_merge<<<PTOT / 32, 256>>>(x);

    // K5: conv1x1 128->1024 with fused LN2 (y_in at slot1..8)
    k_gemm_in<<<dim3(PTOT / 128, 8), 256>>>(w_in, ln2w, ln2b);

    // K6: depthwise 3x3 + GELU gate (y_g at slot9..12)
    k_dwconv<<<(PTOT * 512) / 256, 256>>>(w_dw);

    // K7: conv1x1 512->128 + residual -> d_out (NCHW)
    k_gemm_out<<<dim3(PTOT / 128, 1), 256>>>(w_out, outp);
}

// round 2
// speedup vs baseline: 1.4212x; 1.4212x over previous
#include <cuda_runtime.h>
#include <math.h>

#define BATCH 4
#define CHN   128
#define HDIM  176
#define WDIM  176
#define HW    30976            // 176*176
#define PTOT  123904           // BATCH*HW
#define NWIN  1936             // 44*44
#define PB    3964928ULL       // per-batch plane = 128*30976
#define SLOT  15859712ULL      // PTOT*128
#define ST    137              // smem row stride (floats)

// scratch slots:
// s0: Aq -> later x1        s1: Akv -> AO -> y_in[0]
// s2: Q  s3: K  s4: V       s1..s8: y_in (P x 1024)
// s9..s12: y_g (P x 512)
__device__ float g_s[13ULL * SLOT];
__device__ float g_mu2[PTOT];
__device__ float g_rstd2[PTOT];

// ---------------------------------------------------------------------------
// helpers: tf32 convert + m16n8k8 tf32 MMA
// ---------------------------------------------------------------------------
__device__ __forceinline__ unsigned f2t(float f) {
    unsigned u;
    asm("cvt.rna.tf32.f32 %0, %1;" : "=r"(u) : "f"(f));
    return u;
}
__device__ __forceinline__ void mma8(float* d, const unsigned* a, const unsigned* b) {
    asm volatile(
        "mma.sync.aligned.m16n8k8.row.col.f32.tf32.tf32.f32 "
        "{%0,%1,%2,%3},{%4,%5,%6,%7},{%8,%9},{%0,%1,%2,%3};"
        : "+f"(d[0]), "+f"(d[1]), "+f"(d[2]), "+f"(d[3])
        : "r"(a[0]), "r"(a[1]), "r"(a[2]), "r"(a[3]), "r"(b[0]), "r"(b[1]));
}

__device__ __forceinline__ void mma_compute(
    const unsigned* As, const unsigned* Bs, float acc[4][4][4],
    int t, int g, int wm, int wn)
{
    #pragma unroll
    for (int ks = 0; ks < 2; ks++) {
        unsigned af[4][4], bf[4][2];
        #pragma unroll
        for (int tm = 0; tm < 4; tm++) {
            int row = wm * 64 + tm * 16 + g;
            af[tm][0] = As[(ks * 8 + t) * ST + row];
            af[tm][1] = As[(ks * 8 + t) * ST + row + 8];
            af[tm][2] = As[(ks * 8 + 4 + t) * ST + row];
            af[tm][3] = As[(ks * 8 + 4 + t) * ST + row + 8];
        }
        #pragma unroll
        for (int tn = 0; tn < 4; tn++) {
            int col = wn * 32 + tn * 8 + g;
            bf[tn][0] = Bs[(ks * 8 + t) * ST + col];
            bf[tn][1] = Bs[(ks * 8 + 4 + t) * ST + col];
        }
        #pragma unroll
        for (int tm = 0; tm < 4; tm++)
            #pragma unroll
            for (int tn = 0; tn < 4; tn++)
                mma8(acc[tm][tn], af[tm], bf[tn]);
    }
}

// ---------------------------------------------------------------------------
// K1: LN1(x), bilinear mask/edge upsample, A_kv = LN1(x)*mask_r (slot1),
//     A_q = edge_r (slot0). NHWC rows per pixel.
// ---------------------------------------------------------------------------
__global__ void __launch_bounds__(256) k_prep(
    const float* __restrict__ x, const float* __restrict__ mask,
    const float* __restrict__ edge, const float* __restrict__ ln1w,
    const float* __restrict__ ln1b)
{
    __shared__ float xs[128 * 33];
    __shared__ float red[264], red2[264];
    __shared__ float ms[32], mu_s[32], rs_s[32];
    __shared__ int   cy0[32], cy1[32], cx0[32], cx1[32];
    __shared__ float cwy[32], cwx[32];

    int p0 = blockIdx.x * 32;
    int b = p0 / HW, hw0 = p0 % HW;
    const float* xb = x + (size_t)b * PB;

    for (int e = threadIdx.x; e < 4096; e += 256) {
        int c = e >> 5, px = e & 31;
        xs[c * 33 + px] = xb[(size_t)c * HW + hw0 + px];
    }
    if (threadIdx.x < 32) {
        int px = threadIdx.x;
        int hw = hw0 + px;
        int h2 = hw / WDIM, w2 = hw % WDIM;
        float fy = 0.25f * h2 - 0.375f; int iy = (int)floorf(fy); float ty = fy - iy;
        float fx = 0.25f * w2 - 0.375f; int ix = (int)floorf(fx); float tx = fx - ix;
        int y0 = iy < 0 ? 0 : iy, y1 = (iy + 1 > 43) ? 43 : iy + 1;
        int x0 = ix < 0 ? 0 : ix, x1 = (ix + 1 > 43) ? 43 : ix + 1;
        cy0[px] = y0; cy1[px] = y1; cx0[px] = x0; cx1[px] = x1;
        cwy[px] = ty; cwx[px] = tx;
        const float* mb = mask + b * NWIN;
        ms[px] = (1.f - ty) * ((1.f - tx) * mb[y0 * 44 + x0] + tx * mb[y0 * 44 + x1])
               +        ty  * ((1.f - tx) * mb[y1 * 44 + x0] + tx * mb[y1 * 44 + x1]);
    }
    __syncthreads();
    {
        int px = threadIdx.x & 31, j = threadIdx.x >> 5;
        float s = 0.f, s2 = 0.f;
        #pragma unroll
        for (int i = 0; i < 16; i++) {
            float v = xs[(j * 16 + i) * 33 + px];
            s += v; s2 += v * v;
        }
        red[j * 33 + px] = s; red2[j * 33 + px] = s2;
    }
    __syncthreads();
    if (threadIdx.x < 32) {
        int px = threadIdx.x; float s = 0.f, s2 = 0.f;
        #pragma unroll
        for (int j = 0; j < 8; j++) { s += red[j * 33 + px]; s2 += red2[j * 33 + px]; }
        float mu = s * (1.f / 128.f);
        float var = s2 * (1.f / 128.f) - mu * mu;
        mu_s[px] = mu; rs_s[px] = rsqrtf(var + 1e-5f);
    }
    __syncthreads();
    float* Akv = g_s + SLOT;
    for (int e = threadIdx.x; e < 4096; e += 256) {
        int px = e >> 7, c = e & 127;
        float v = (xs[c * 33 + px] - mu_s[px]) * rs_s[px] * ln1w[c] + ln1b[c];
        Akv[(size_t)(p0 + px) * 128 + c] = v * ms[px];
    }
    __syncthreads();
    for (int e = threadIdx.x; e < 4096; e += 256) {
        int c = e >> 5, px = e & 31;
        const float* eb = edge + ((size_t)b * 128 + c) * NWIN;
        float ty = cwy[px], tx = cwx[px];
        float v = (1.f - ty) * ((1.f - tx) * eb[cy0[px] * 44 + cx0[px]] + tx * eb[cy0[px] * 44 + cx1[px]])
                +        ty  * ((1.f - tx) * eb[cy1[px] * 44 + cx0[px]] + tx * eb[cy1[px] * 44 + cx1[px]]);
        xs[c * 33 + px] = v;
    }
    __syncthreads();
    float* Aq = g_s;
    for (int e = threadIdx.x; e < 4096; e += 256) {
        int px = e >> 7, c = e & 127;
        Aq[(size_t)(p0 + px) * 128 + c] = xs[c * 33 + px];
    }
}

// ---------------------------------------------------------------------------
// K2: generic TF32 MMA GEMM, slot A (row-major [m][KD]) x Wt ([n][KD]) -> slot C.
// ---------------------------------------------------------------------------
template<int KD>
__global__ void __launch_bounds__(256) k_mma_ab(
    int aslot, const float* __restrict__ Wt, int cslot, int ndtot)
{
    __shared__ unsigned As[2][16 * ST], Bs[2][16 * ST];
    const float* A = g_s + (size_t)aslot * SLOT;
    float* C = g_s + (size_t)cslot * SLOT;
    int m0 = blockIdx.x * 128, n0 = blockIdx.y * 128;
    int tid = threadIdx.x, lane = tid & 31, warp = tid >> 5;
    int wm = warp >> 2, wn = warp & 3, t = lane & 3, g = lane >> 2;
    float acc[4][4][4];
    #pragma unroll
    for (int i = 0; i < 4; i++)
        #pragma unroll
        for (int j = 0; j < 4; j++)
            #pragma unroll
            for (int k = 0; k < 4; k++) acc[i][j][k] = 0.f;
    float ra[8], rb[8];

    #pragma unroll
    for (int i = 0; i < 8; i++) {
        int idx = tid + i * 256; int r = idx >> 4, kk = idx & 15;
        ra[i] = A[(size_t)(m0 + r) * KD + kk];
        rb[i] = Wt[(size_t)(n0 + r) * KD + kk];
    }
    #pragma unroll
    for (int i = 0; i < 8; i++) {
        int idx = tid + i * 256; int r = idx >> 4, kk = idx & 15;
        As[0][kk * ST + r] = f2t(ra[i]);
        Bs[0][kk * ST + r] = f2t(rb[i]);
    }
    __syncthreads();

    const int KT = KD / 16;
    #pragma unroll 2
    for (int kt = 0; kt < KT; kt++) {
        int buf = kt & 1;
        if (kt + 1 < KT) {
            int k0 = (kt + 1) * 16;
            #pragma unroll
            for (int i = 0; i < 8; i++) {
                int idx = tid + i * 256; int r = idx >> 4, kk = idx & 15;
                ra[i] = A[(size_t)(m0 + r) * KD + k0 + kk];
                rb[i] = Wt[(size_t)(n0 + r) * KD + k0 + kk];
            }
        }
        mma_compute(As[buf], Bs[buf], acc, t, g, wm, wn);
        if (kt + 1 < KT) {
            #pragma unroll
            for (int i = 0; i < 8; i++) {
                int idx = tid + i * 256; int r = idx >> 4, kk = idx & 15;
                As[buf ^ 1][kk * ST + r] = f2t(ra[i]);
                Bs[buf ^ 1][kk * ST + r] = f2t(rb[i]);
            }
        }
        __syncthreads();
    }

    #pragma unroll
    for (int tm = 0; tm < 4; tm++)
        #pragma unroll
        for (int tn = 0; tn < 4; tn++) {
            int m = m0 + wm * 64 + tm * 16 + g;
            int n = n0 + wn * 32 + tn * 8 + 2 * t;
            *(float2*)(C + (size_t)m * ndtot + n) = make_float2(acc[tm][tn][0], acc[tm][tn][1]);
            *(float2*)(C + (size_t)(m + 8) * ndtot + n) = make_float2(acc[tm][tn][2], acc[tm][tn][3]);
        }
}

// ---------------------------------------------------------------------------
// K3: per-(window,token) channel attention -> AO in merged layout (slot1).
// ---------------------------------------------------------------------------
__global__ void __launch_bounds__(256) k_attn()
{
    __shared__ float outs[32 * 129];
    __shared__ float buf[8 * 640];
    int bid = blockIdx.x;
    int chunk = bid % 61;
    int n = (bid / 61) % 16;
    int b = bid / (61 * 16);
    int ihw0 = chunk * 32;
    const float* Q  = g_s + 2 * SLOT;
    const float* Kp = g_s + 3 * SLOT;
    const float* V  = g_s + 4 * SLOT;
    float* AO = g_s + SLOT;
    int warp = threadIdx.x >> 5, lane = threadIdx.x & 31;
    float* qs = buf + warp * 640;
    float* ks = qs + 128;
    float* vs = qs + 256;
    float* ds = qs + 384;

    for (int it = 0; it < 4; it++) {
        int g = it * 8 + warp;
        int ihw = ihw0 + g;
        if (ihw < NWIN) {
            int ih = ihw / 44, iw = ihw % 44;
            int h2 = ih * 4 + (n >> 2), w2 = iw * 4 + (n & 3);
            size_t p = (size_t)b * HW + (size_t)h2 * 176 + w2;
            for (int i = lane; i < 128; i += 32) {
                qs[i] = Q[p * 128 + i];
                ks[i] = Kp[p * 128 + i];
                vs[i] = V[p * 128 + i];
            }
            __syncwarp();
            for (int e = lane; e < 256; e += 32) {
                int j = e >> 4, kk = e & 15;
                float s = 0.f;
                #pragma unroll
                for (int i = 0; i < 8; i++) s += qs[i * 16 + j] * ks[i * 16 + kk];
                ds[e] = s * 0.25f;
            }
            __syncwarp();
            if (lane < 16) {
                float mx = -1e30f;
                #pragma unroll
                for (int kk = 0; kk < 16; kk++) mx = fmaxf(mx, ds[lane * 16 + kk]);
                float sm = 0.f;
                #pragma unroll
                for (int kk = 0; kk < 16; kk++) {
                    float ev = __expf(ds[lane * 16 + kk] - mx);
                    ds[lane * 16 + kk] = ev; sm += ev;
                }
                float inv = 1.f / sm;
                #pragma unroll
                for (int kk = 0; kk < 16; kk++) ds[lane * 16 + kk] *= inv;
            }
            __syncwarp();
            for (int ch = lane; ch < 128; ch += 32) {
                int i = ch >> 4, j = ch & 15;
                float s = 0.f;
                #pragma unroll
                for (int kk = 0; kk < 16; kk++) s += ds[j * 16 + kk] * vs[i * 16 + kk];
                outs[g * 129 + ch] = s;
            }
        }
    }
    __syncthreads();
    size_t base = ((size_t)b * 2048 + (size_t)n * 128) * 1936 + ihw0;
    for (int e = threadIdx.x; e < 4096; e += 256) {
        int ch = e >> 5, g = e & 31;
        if (ihw0 + g < NWIN)
            AO[base + (size_t)ch * 1936 + g] = outs[g * 129 + ch];
    }
}

// ---------------------------------------------------------------------------
// K4: x1 = x + AO (elementwise, layout identity) + LN2 stats.
// ---------------------------------------------------------------------------
__global__ void __launch_bounds__(256) k_merge(const float* __restrict__ x)
{
    __shared__ float red[264], red2[264];
    int p0 = blockIdx.x * 32;
    int b = p0 / HW, hw0 = p0 % HW;
    int px = threadIdx.x & 31, j = threadIdx.x >> 5;
    const float* AO = g_s + SLOT;
    float* x1 = g_s;
    size_t base = (size_t)b * PB + hw0 + px;
    float s = 0.f, s2 = 0.f;
    #pragma unroll
    for (int i = 0; i < 16; i++) {
        int c = j * 16 + i;
        size_t idx = base + (size_t)c * HW;
        float v = x[idx] + AO[idx];
        x1[idx] = v; s += v; s2 += v * v;
    }
    red[j * 33 + px] = s; red2[j * 33 + px] = s2;
    __syncthreads();
    if (threadIdx.x < 32) {
        float ss = 0.f, ss2 = 0.f;
        #pragma unroll
        for (int j2 = 0; j2 < 8; j2++) { ss += red[j2 * 33 + threadIdx.x]; ss2 += red2[j2 * 33 + threadIdx.x]; }
        float mu = ss * (1.f / 128.f);
        float var = ss2 * (1.f / 128.f) - mu * mu;
        g_mu2[p0 + threadIdx.x] = mu;
        g_rstd2[p0 + threadIdx.x] = rsqrtf(var + 1e-5f);
    }
}

// ---------------------------------------------------------------------------
// K5: conv_in TF32 MMA GEMM, A = LN2(x1) from NCHW (LN fused in A-load),
//     C = y_in [P][1024] at slot1.
// ---------------------------------------------------------------------------
__global__ void __launch_bounds__(256) k_mma_in(
    const float* __restrict__ Wt, const float* __restrict__ ln2w,
    const float* __restrict__ ln2b)
{
    __shared__ unsigned As[2][16 * ST], Bs[2][16 * ST];
    __shared__ float w2s[128], b2s[128];
    const float* x1 = g_s;
    float* C = g_s + SLOT;
    int m0 = blockIdx.x * 128, n0 = blockIdx.y * 128;
    int b = m0 / HW, hw0 = m0 % HW;
    int tid = threadIdx.x, lane = tid & 31, warp = tid >> 5;
    int wm = warp >> 2, wn = warp & 3, t = lane & 3, g = lane >> 2;
    int rA = tid & 127;
    if (tid < 128) { w2s[tid] = ln2w[tid]; b2s[tid] = ln2b[tid]; }
    float mu = g_mu2[m0 + rA], rs = g_rstd2[m0 + rA];
    float acc[4][4][4];
    #pragma unroll
    for (int i = 0; i < 4; i++)
        #pragma unroll
        for (int j = 0; j < 4; j++)
            #pragma unroll
            for (int k = 0; k < 4; k++) acc[i][j][k] = 0.f;
    float ra[8], rb[8];
    __syncthreads();

    #pragma unroll
    for (int i = 0; i < 8; i++) {
        int kk = i * 2 + (tid >> 7);
        ra[i] = x1[((size_t)b * 128 + kk) * HW + hw0 + rA];
        int idx = tid + i * 256; int r = idx >> 4, k2 = idx & 15;
        rb[i] = Wt[(size_t)(n0 + r) * 128 + k2];
    }
    #pragma unroll
    for (int i = 0; i < 8; i++) {
        int kk = i * 2 + (tid >> 7);
        As[0][kk * ST + rA] = f2t((ra[i] - mu) * rs * w2s[kk] + b2s[kk]);
        int idx = tid + i * 256; int r = idx >> 4, k2 = idx & 15;
        Bs[0][k2 * ST + r] = f2t(rb[i]);
    }
    __syncthreads();

    #pragma unroll 2
    for (int kt = 0; kt < 8; kt++) {
        int buf = kt & 1;
        if (kt + 1 < 8) {
            int k0 = (kt + 1) * 16;
            #pragma unroll
            for (int i = 0; i < 8; i++) {
                int kk = i * 2 + (tid >> 7);
                ra[i] = x1[((size_t)b * 128 + k0 + kk) * HW + hw0 + rA];
                int idx = tid + i * 256; int r = idx >> 4, k2 = idx & 15;
                rb[i] = Wt[(size_t)(n0 + r) * 128 + k0 + k2];
            }
        }
        mma_compute(As[buf], Bs[buf], acc, t, g, wm, wn);
        if (kt + 1 < 8) {
            int k0 = (kt + 1) * 16;
            #pragma unroll
            for (int i = 0; i < 8; i++) {
                int kk = i * 2 + (tid >> 7);
                As[buf ^ 1][kk * ST + rA] = f2t((ra[i] - mu) * rs * w2s[k0 + kk] + b2s[k0 + kk]);
                int idx = tid + i * 256; int r = idx >> 4, k2 = idx & 15;
                Bs[buf ^ 1][k2 * ST + r] = f2t(rb[i]);
            }
        }
        __syncthreads();
    }

    #pragma unroll
    for (int tm = 0; tm < 4; tm++)
        #pragma unroll
        for (int tn = 0; tn < 4; tn++) {
            int m = m0 + wm * 64 + tm * 16 + g;
            int n = n0 + wn * 32 + tn * 8 + 2 * t;
            *(float2*)(C + (size_t)m * 1024 + n) = make_float2(acc[tm][tn][0], acc[tm][tn][1]);
            *(float2*)(C + (size_t)(m + 8) * 1024 + n) = make_float2(acc[tm][tn][2], acc[tm][tn][3]);
        }
}

// ---------------------------------------------------------------------------
// K6: depthwise 3x3 + exact GELU gate. y_g[p][ch] = gelu(dw(y1)) * dw(y2).
// ---------------------------------------------------------------------------
__global__ void __launch_bounds__(256) k_dwconv(const float* __restrict__ wdw)
{
    int idx = blockIdx.x * 256 + threadIdx.x;
    int ch = idx & 511;
    int p = idx >> 9;
    int b = p / HW, hw = p % HW;
    int h = hw / 176, w = hw % 176;
    const float* yin = g_s + SLOT;
    float* yg = g_s + 9 * SLOT;
    float wa[9], wb[9];
    #pragma unroll
    for (int t = 0; t < 9; t++) {
        wa[t] = __ldg(&wdw[ch * 9 + t]);
        wb[t] = __ldg(&wdw[(ch + 512) * 9 + t]);
    }
    float a = 0.f, gg = 0.f;
    #pragma unroll
    for (int dy = -1; dy <= 1; dy++) {
        int hh = h + dy; if (hh < 0 || hh >= 176) continue;
        #pragma unroll
        for (int dx = -1; dx <= 1; dx++) {
            int ww2 = w + dx; if (ww2 < 0 || ww2 >= 176) continue;
            size_t q = ((size_t)b * HW + (size_t)hh * 176 + ww2) * 1024;
            int t = (dy + 1) * 3 + dx + 1;
            a  += yin[q + ch] * wa[t];
            gg += yin[q + 512 + ch] * wb[t];
        }
    }
    float ge = 0.5f * a * (1.f + erff(a * 0.70710678118654752f));
    yg[(size_t)p * 512 + ch] = ge * gg;
}

// ---------------------------------------------------------------------------
// K7: conv_out TF32 MMA GEMM (K=512) + residual -> final NCHW output.
// ---------------------------------------------------------------------------
__global__ void __launch_bounds__(256) k_mma_out(
    const float* __restrict__ Wt, float* __restrict__ outp)
{
    __shared__ unsigned As[2][16 * ST], Bs[2][16 * ST];
    const float* A = g_s + 9 * SLOT;   // y_g [P][512]
    const float* x1 = g_s;             // NCHW
    int m0 = blockIdx.x * 128;
    int b = m0 / HW, hw0 = m0 % HW;
    int tid = threadIdx.x, lane = tid & 31, warp = tid >> 5;
    int wm = warp >> 2, wn = warp & 3, t = lane & 3, g = lane >> 2;
    float acc[4][4][4];
    #pragma unroll
    for (int i = 0; i < 4; i++)
        #pragma unroll
        for (int j = 0; j < 4; j++)
            #pragma unroll
            for (int k = 0; k < 4; k++) acc[i][j][k] = 0.f;
    float ra[8], rb[8];

    #pragma unroll
    for (int i = 0; i < 8; i++) {
        int idx = tid + i * 256; int r = idx >> 4, kk = idx & 15;
        ra[i] = A[(size_t)(m0 + r) * 512 + kk];
        rb[i] = Wt[(size_t)r * 512 + kk];
    }
    #pragma unroll
    for (int i = 0; i < 8; i++) {
        int idx = tid + i * 256; int r = idx >> 4, kk = idx & 15;
        As[0][kk * ST + r] = f2t(ra[i]);
        Bs[0][kk * ST + r] = f2t(rb[i]);
    }
    __syncthreads();

    #pragma unroll 2
    for (int kt = 0; kt < 32; kt++) {
        int buf = kt & 1;
        if (kt + 1 < 32) {
            int k0 = (kt + 1) * 16;
            #pragma unroll
            for (int i = 0; i < 8; i++) {
                int idx = tid + i * 256; int r = idx >> 4, kk = idx & 15;
                ra[i] = A[(size_t)(m0 + r) * 512 + k0 + kk];
                rb[i] = Wt[(size_t)r * 512 + k0 + kk];
            }
        }
        mma_compute(As[buf], Bs[buf], acc, t, g, wm, wn);
        if (kt + 1 < 32) {
            #pragma unroll
            for (int i = 0; i < 8; i++) {
                int idx = tid + i * 256; int r = idx >> 4, kk = idx & 15;
                As[buf ^ 1][kk * ST + r] = f2t(ra[i]);
                Bs[buf ^ 1][kk * ST + r] = f2t(rb[i]);
            }
        }
        __syncthreads();
    }

    #pragma unroll
    for (int tm = 0; tm < 4; tm++)
        #pragma unroll
        for (int tn = 0; tn < 4; tn++) {
            int mrow = wm * 64 + tm * 16 + g;
            int n = wn * 32 + tn * 8 + 2 * t;
            size_t a0 = ((size_t)b * 128 + n) * HW + hw0 + mrow;
            outp[a0]          = x1[a0] + acc[tm][tn][0];
            outp[a0 + HW]     = x1[a0 + HW] + acc[tm][tn][1];
            outp[a0 + 8]      = x1[a0 + 8] + acc[tm][tn][2];
            outp[a0 + HW + 8] = x1[a0 + HW + 8] + acc[tm][tn][3];
        }
}

// ---------------------------------------------------------------------------
extern "C" void kernel_launch(void* const* d_in, const int* in_sizes, int n_in,
                              void* d_out, int out_size)
{
    const float* x    = (const float*)d_in[0];
    const float* mask = (const float*)d_in[1];
    const float* edge = (const float*)d_in[2];
    const float* ln1w = (const float*)d_in[3];
    const float* ln1b = (const float*)d_in[4];
    const float* Wq   = (const float*)d_in[5];
    const float* Wk   = (const float*)d_in[6];
    const float* Wv   = (const float*)d_in[7];
    const float* ln2w = (const float*)d_in[8];
    const float* ln2b = (const float*)d_in[9];
    const float* w_in = (const float*)d_in[10];
    const float* w_dw = (const float*)d_in[11];
    const float* w_out= (const float*)d_in[12];
    float* outp = (float*)d_out;

    // K1: LN1 + resize + window inputs (Aq slot0, Akv slot1)
    k_prep<<<PTOT / 32, 256>>>(x, mask, edge, ln1w, ln1b);

    // K2: Q/K/V TF32 GEMMs (M=123904, N=128, K=128)
    k_mma_ab<128><<<dim3(PTOT / 128, 1), 256>>>(0, Wq, 2, 128);
    k_mma_ab<128><<<dim3(PTOT / 128, 1), 256>>>(1, Wk, 3, 128);
    k_mma_ab<128><<<dim3(PTOT / 128, 1), 256>>>(1, Wv, 4, 128);

    // K3: channel attention -> AO (slot1, merged layout)
    k_attn<<<4 * 16 * 61, 256>>>();

    // K4: x1 = x + AO + LN2 stats
    k_merge<<<PTOT / 32, 256>>>(x);

    // K5: conv1x1 128->1024 TF32 GEMM with fused LN2 (y_in at slot1..8)
    k_mma_in<<<dim3(PTOT / 128, 8), 256>>>(w_in, ln2w, ln2b);

    // K6: depthwise 3x3 + GELU gate (y_g at slot9..12)
    k_dwconv<<<(PTOT * 512) / 256, 256>>>(w_dw);

    // K7: conv1x1 512->128 TF32 GEMM + residual -> d_out (NCHW)
    k_mma_out<<<dim3(PTOT / 128, 1), 256>>>(w_out, outp);
}

// round 3
// speedup vs baseline: 2.7805x; 1.9565x over previous
#include <cuda_runtime.h>
#include <cuda_bf16.h>
#include <math.h>

#define BATCH 4
#define HW    30976            // 176*176
#define PTOT  123904           // BATCH*HW
#define NWIN  1936             // 44*44
#define PB    3964928ULL       // per-batch plane = 128*30976

// uint-unit offsets into the single scratch buffer
#define OFF_AQ    0ULL
#define OFF_AKV   7929856ULL
#define OFF_AO    15859712ULL
#define OFF_Q     31719424ULL
#define OFF_K     47579136ULL
#define OFF_V     63438848ULL
#define OFF_X1    79298560ULL
#define OFF_X1LN  95158272ULL
#define OFF_YIN   103088128ULL
#define OFF_YG    166526976ULL
#define OFF_WB    198246400ULL
#define TOT_U     198369280ULL

__device__ unsigned g_u[TOT_U];

// ---------------------------------------------------------------------------
// helpers
// ---------------------------------------------------------------------------
__device__ __forceinline__ unsigned pk(float lo, float hi) {
    unsigned r;
    asm("cvt.rn.bf16x2.f32 %0, %1, %2;" : "=r"(r) : "f"(hi), "f"(lo));
    return r;
}
__device__ __forceinline__ float2 bf2f(unsigned u) {
    __nv_bfloat162 h = *reinterpret_cast<__nv_bfloat162*>(&u);
    return __bfloat1622float2(h);
}
__device__ __forceinline__ void mma16(float* d, const unsigned* a, const unsigned* b) {
    asm volatile(
        "mma.sync.aligned.m16n8k16.row.col.f32.bf16.bf16.f32 "
        "{%0,%1,%2,%3},{%4,%5,%6,%7},{%8,%9},{%0,%1,%2,%3};"
        : "+f"(d[0]), "+f"(d[1]), "+f"(d[2]), "+f"(d[3])
        : "r"(a[0]), "r"(a[1]), "r"(a[2]), "r"(a[3]), "r"(b[0]), "r"(b[1]));
}

// one k16 stage: smem layout [kpair 0..7][item 0..127], stride 136
__device__ __forceinline__ void mma_stage(
    const unsigned* As, const unsigned* Bs, float acc[4][4][4],
    int t, int g, int wm, int wn)
{
    unsigned af[4][4], bf[4][2];
    #pragma unroll
    for (int tm = 0; tm < 4; tm++) {
        int row = wm * 64 + tm * 16 + g;
        af[tm][0] = As[t * 136 + row];
        af[tm][1] = As[t * 136 + row + 8];
        af[tm][2] = As[(t + 4) * 136 + row];
        af[tm][3] = As[(t + 4) * 136 + row + 8];
    }
    #pragma unroll
    for (int tn = 0; tn < 4; tn++) {
        int col = wn * 32 + tn * 8 + g;
        bf[tn][0] = Bs[t * 136 + col];
        bf[tn][1] = Bs[(t + 4) * 136 + col];
    }
    #pragma unroll
    for (int tm = 0; tm < 4; tm++)
        #pragma unroll
        for (int tn = 0; tn < 4; tn++)
            mma16(acc[tm][tn], af[tm], bf[tn]);
}

// ---------------------------------------------------------------------------
// K0: weight prep -> packed bf16x2, pairs along k.
// WB layout: WqP[128][64] WkP WvP | WinP[1024][64] | WoutP[128][256]
// ---------------------------------------------------------------------------
__global__ void k_wprep(const float* __restrict__ Wq, const float* __restrict__ Wk,
                        const float* __restrict__ Wv, const float* __restrict__ win,
                        const float* __restrict__ wout)
{
    int idx = blockIdx.x * 256 + threadIdx.x;
    if (idx >= 122880) return;
    unsigned* WB = g_u + OFF_WB;
    if (idx < 8192) {
        int n = idx >> 6, kp = idx & 63;
        WB[idx] = pk(Wq[n * 128 + 2 * kp], Wq[n * 128 + 2 * kp + 1]);
    } else if (idx < 16384) {
        int j = idx - 8192; int n = j >> 6, kp = j & 63;
        WB[idx] = pk(Wk[n * 128 + 2 * kp], Wk[n * 128 + 2 * kp + 1]);
    } else if (idx < 24576) {
        int j = idx - 16384; int n = j >> 6, kp = j & 63;
        WB[idx] = pk(Wv[n * 128 + 2 * kp], Wv[n * 128 + 2 * kp + 1]);
    } else if (idx < 90112) {
        int j = idx - 24576; int n = j >> 6, kp = j & 63;
        WB[idx] = pk(win[n * 128 + 2 * kp], win[n * 128 + 2 * kp + 1]);
    } else {
        int j = idx - 90112; int n = j >> 8, kp = j & 255;
        WB[idx] = pk(wout[n * 512 + 2 * kp], wout[n * 512 + 2 * kp + 1]);
    }
}

// ---------------------------------------------------------------------------
// K1: LN1(x), bilinear mask/edge upsample; writes packed bf16x2 rows:
//     Akv_u[p][64] = pack(LN1(x)*mask_r),  Aq_u[p][64] = pack(edge_r)
// ---------------------------------------------------------------------------
__global__ void __launch_bounds__(256) k_prep(
    const float* __restrict__ x, const float* __restrict__ mask,
    const float* __restrict__ edge, const float* __restrict__ ln1w,
    const float* __restrict__ ln1b)
{
    __shared__ float xs[128 * 33];
    __shared__ float red[264], red2[264];
    __shared__ float ms[32], mu_s[32], rs_s[32];
    __shared__ int   cy0[32], cy1[32], cx0[32], cx1[32];
    __shared__ float cwy[32], cwx[32];
    __shared__ float w1s[128], b1s[128];

    int p0 = blockIdx.x * 32;
    int b = p0 / HW, hw0 = p0 % HW;
    const float* xb = x + (size_t)b * PB;
    if (threadIdx.x < 128) { w1s[threadIdx.x] = ln1w[threadIdx.x]; b1s[threadIdx.x] = ln1b[threadIdx.x]; }

    for (int e = threadIdx.x; e < 4096; e += 256) {
        int c = e >> 5, px = e & 31;
        xs[c * 33 + px] = xb[(size_t)c * HW + hw0 + px];
    }
    if (threadIdx.x < 32) {
        int px = threadIdx.x;
        int hw = hw0 + px;
        int h2 = hw / 176, w2 = hw % 176;
        float fy = 0.25f * h2 - 0.375f; int iy = (int)floorf(fy); float ty = fy - iy;
        float fx = 0.25f * w2 - 0.375f; int ix = (int)floorf(fx); float tx = fx - ix;
        int y0 = iy < 0 ? 0 : iy, y1 = (iy + 1 > 43) ? 43 : iy + 1;
        int x0 = ix < 0 ? 0 : ix, x1 = (ix + 1 > 43) ? 43 : ix + 1;
        cy0[px] = y0; cy1[px] = y1; cx0[px] = x0; cx1[px] = x1;
        cwy[px] = ty; cwx[px] = tx;
        const float* mb = mask + b * NWIN;
        ms[px] = (1.f - ty) * ((1.f - tx) * mb[y0 * 44 + x0] + tx * mb[y0 * 44 + x1])
               +        ty  * ((1.f - tx) * mb[y1 * 44 + x0] + tx * mb[y1 * 44 + x1]);
    }
    __syncthreads();
    {
        int px = threadIdx.x & 31, j = threadIdx.x >> 5;
        float s = 0.f, s2 = 0.f;
        #pragma unroll
        for (int i = 0; i < 16; i++) {
            float v = xs[(j * 16 + i) * 33 + px];
            s += v; s2 += v * v;
        }
        red[j * 33 + px] = s; red2[j * 33 + px] = s2;
    }
    __syncthreads();
    if (threadIdx.x < 32) {
        int px = threadIdx.x; float s = 0.f, s2 = 0.f;
        #pragma unroll
        for (int j = 0; j < 8; j++) { s += red[j * 33 + px]; s2 += red2[j * 33 + px]; }
        float mu = s * (1.f / 128.f);
        float var = s2 * (1.f / 128.f) - mu * mu;
        mu_s[px] = mu; rs_s[px] = rsqrtf(var + 1e-5f);
    }
    __syncthreads();
    unsigned* Akv = g_u + OFF_AKV;
    for (int e = threadIdx.x; e < 2048; e += 256) {
        int px = e >> 6, kp = e & 63;
        int c0 = 2 * kp;
        float v0 = ((xs[c0 * 33 + px] - mu_s[px]) * rs_s[px] * w1s[c0] + b1s[c0]) * ms[px];
        float v1 = ((xs[(c0 + 1) * 33 + px] - mu_s[px]) * rs_s[px] * w1s[c0 + 1] + b1s[c0 + 1]) * ms[px];
        Akv[(size_t)(p0 + px) * 64 + kp] = pk(v0, v1);
    }
    __syncthreads();
    for (int e = threadIdx.x; e < 4096; e += 256) {
        int c = e >> 5, px = e & 31;
        const float* eb = edge + ((size_t)b * 128 + c) * NWIN;
        float ty = cwy[px], tx = cwx[px];
        float v = (1.f - ty) * ((1.f - tx) * eb[cy0[px] * 44 + cx0[px]] + tx * eb[cy0[px] * 44 + cx1[px]])
                +        ty  * ((1.f - tx) * eb[cy1[px] * 44 + cx0[px]] + tx * eb[cy1[px] * 44 + cx1[px]]);
        xs[c * 33 + px] = v;
    }
    __syncthreads();
    unsigned* Aq = g_u + OFF_AQ;
    for (int e = threadIdx.x; e < 2048; e += 256) {
        int px = e >> 6, kp = e & 63;
        Aq[(size_t)(p0 + px) * 64 + kp] = pk(xs[(2 * kp) * 33 + px], xs[(2 * kp + 1) * 33 + px]);
    }
}

// ---------------------------------------------------------------------------
// K2: generic bf16 MMA GEMM. A packed [M][KD/2], B packed [n][KD/2].
// EPI=0: fp32 C [M][Nd].  EPI=1: packed bf16x2 C [M][Nd/2].
// ---------------------------------------------------------------------------
template<int KD, int EPI>
__global__ void __launch_bounds__(256, 2) k_mma_g(
    const unsigned* __restrict__ Au, const unsigned* __restrict__ Bu,
    unsigned* __restrict__ Cu, int Nd)
{
    const int KP = KD / 2, NST = KD / 16;
    __shared__ unsigned Ap[2][8 * 136], Bp[2][8 * 136];
    int m0 = blockIdx.x * 128, n0 = blockIdx.y * 128;
    int tid = threadIdx.x, lane = tid & 31, warp = tid >> 5;
    int wm = warp >> 2, wn = warp & 3, t = lane & 3, g = lane >> 2;
    float acc[4][4][4];
    #pragma unroll
    for (int i = 0; i < 4; i++)
        #pragma unroll
        for (int j = 0; j < 4; j++)
            #pragma unroll
            for (int k = 0; k < 4; k++) acc[i][j][k] = 0.f;
    unsigned ra[4], rb[4];

    #pragma unroll
    for (int i = 0; i < 4; i++) {
        int idx = tid + i * 256; int kk = idx & 7, m = idx >> 3;
        ra[i] = Au[(size_t)(m0 + m) * KP + kk];
        rb[i] = Bu[(size_t)(n0 + m) * KP + kk];
    }
    #pragma unroll
    for (int i = 0; i < 4; i++) {
        int idx = tid + i * 256; int kk = idx & 7, m = idx >> 3;
        Ap[0][kk * 136 + m] = ra[i];
        Bp[0][kk * 136 + m] = rb[i];
    }
    __syncthreads();

    #pragma unroll 2
    for (int ks = 0; ks < NST; ks++) {
        int buf = ks & 1;
        if (ks + 1 < NST) {
            int kb = (ks + 1) * 8;
            #pragma unroll
            for (int i = 0; i < 4; i++) {
                int idx = tid + i * 256; int kk = idx & 7, m = idx >> 3;
                ra[i] = Au[(size_t)(m0 + m) * KP + kb + kk];
                rb[i] = Bu[(size_t)(n0 + m) * KP + kb + kk];
            }
        }
        mma_stage(Ap[buf], Bp[buf], acc, t, g, wm, wn);
        if (ks + 1 < NST) {
            #pragma unroll
            for (int i = 0; i < 4; i++) {
                int idx = tid + i * 256; int kk = idx & 7, m = idx >> 3;
                Ap[buf ^ 1][kk * 136 + m] = ra[i];
                Bp[buf ^ 1][kk * 136 + m] = rb[i];
            }
        }
        __syncthreads();
    }

    #pragma unroll
    for (int tm = 0; tm < 4; tm++)
        #pragma unroll
        for (int tn = 0; tn < 4; tn++) {
            int m = m0 + wm * 64 + tm * 16 + g;
            int n = n0 + wn * 32 + tn * 8 + 2 * t;
            if (EPI == 0) {
                float* C = (float*)Cu;
                *(float2*)(C + (size_t)m * Nd + n) = make_float2(acc[tm][tn][0], acc[tm][tn][1]);
                *(float2*)(C + (size_t)(m + 8) * Nd + n) = make_float2(acc[tm][tn][2], acc[tm][tn][3]);
            } else {
                int np = Nd >> 1;
                Cu[(size_t)m * np + (n >> 1)] = pk(acc[tm][tn][0], acc[tm][tn][1]);
                Cu[(size_t)(m + 8) * np + (n >> 1)] = pk(acc[tm][tn][2], acc[tm][tn][3]);
            }
        }
}

// ---------------------------------------------------------------------------
// K3: per-(window,token) channel attention -> AO fp32 (merged layout).
// ---------------------------------------------------------------------------
__global__ void __launch_bounds__(256) k_attn()
{
    __shared__ float outs[32 * 129];
    __shared__ float buf[8 * 640];
    int bid = blockIdx.x;
    int chunk = bid % 61;
    int n = (bid / 61) % 16;
    int b = bid / (61 * 16);
    int ihw0 = chunk * 32;
    const float* Q  = (const float*)(g_u + OFF_Q);
    const float* Kp = (const float*)(g_u + OFF_K);
    const float* V  = (const float*)(g_u + OFF_V);
    float* AO = (float*)(g_u + OFF_AO);
    int warp = threadIdx.x >> 5, lane = threadIdx.x & 31;
    float* qs = buf + warp * 640;
    float* ks = qs + 128;
    float* vs = qs + 256;
    float* ds = qs + 384;

    for (int it = 0; it < 4; it++) {
        int g = it * 8 + warp;
        int ihw = ihw0 + g;
        if (ihw < NWIN) {
            int ih = ihw / 44, iw = ihw % 44;
            int h2 = ih * 4 + (n >> 2), w2 = iw * 4 + (n & 3);
            size_t p = (size_t)b * HW + (size_t)h2 * 176 + w2;
            for (int i = lane; i < 128; i += 32) {
                qs[i] = Q[p * 128 + i];
                ks[i] = Kp[p * 128 + i];
                vs[i] = V[p * 128 + i];
            }
            __syncwarp();
            for (int e = lane; e < 256; e += 32) {
                int j = e >> 4, kk = e & 15;
                float s = 0.f;
                #pragma unroll
                for (int i = 0; i < 8; i++) s += qs[i * 16 + j] * ks[i * 16 + kk];
                ds[e] = s * 0.25f;
            }
            __syncwarp();
            if (lane < 16) {
                float mx = -1e30f;
                #pragma unroll
                for (int kk = 0; kk < 16; kk++) mx = fmaxf(mx, ds[lane * 16 + kk]);
                float sm = 0.f;
                #pragma unroll
                for (int kk = 0; kk < 16; kk++) {
                    float ev = __expf(ds[lane * 16 + kk] - mx);
                    ds[lane * 16 + kk] = ev; sm += ev;
                }
                float inv = 1.f / sm;
                #pragma unroll
                for (int kk = 0; kk < 16; kk++) ds[lane * 16 + kk] *= inv;
            }
            __syncwarp();
            for (int ch = lane; ch < 128; ch += 32) {
                int i = ch >> 4, j = ch & 15;
                float s = 0.f;
                #pragma unroll
                for (int kk = 0; kk < 16; kk++) s += ds[j * 16 + kk] * vs[i * 16 + kk];
                outs[g * 129 + ch] = s;
            }
        }
    }
    __syncthreads();
    size_t base = ((size_t)b * 2048 + (size_t)n * 128) * 1936 + ihw0;
    for (int e = threadIdx.x; e < 4096; e += 256) {
        int ch = e >> 5, g = e & 31;
        if (ihw0 + g < NWIN)
            AO[base + (size_t)ch * 1936 + g] = outs[g * 129 + ch];
    }
}

// ---------------------------------------------------------------------------
// K4: x1 = x + AO (fp32, layout identity) + LN2 applied & packed -> X1LN.
// ---------------------------------------------------------------------------
__global__ void __launch_bounds__(256) k_merge2(
    const float* __restrict__ x, const float* __restrict__ ln2w,
    const float* __restrict__ ln2b)
{
    __shared__ float red[264], red2[264], mu_s[32], rs_s[32];
    __shared__ float w2s[128], b2s[128];
    int p0 = blockIdx.x * 32;
    int b = p0 / HW, hw0 = p0 % HW;
    int px = threadIdx.x & 31, j = threadIdx.x >> 5;
    if (threadIdx.x < 128) { w2s[threadIdx.x] = ln2w[threadIdx.x]; b2s[threadIdx.x] = ln2b[threadIdx.x]; }
    const float* AO = (const float*)(g_u + OFF_AO);
    float* x1 = (float*)(g_u + OFF_X1);
    size_t base = (size_t)b * PB + hw0 + px;
    float v[16];
    float s = 0.f, s2 = 0.f;
    #pragma unroll
    for (int i = 0; i < 16; i++) {
        int c = j * 16 + i;
        size_t idx = base + (size_t)c * HW;
        float val = x[idx] + AO[idx];
        x1[idx] = val; v[i] = val; s += val; s2 += val * val;
    }
    red[j * 33 + px] = s; red2[j * 33 + px] = s2;
    __syncthreads();
    if (threadIdx.x < 32) {
        float ss = 0.f, ss2 = 0.f;
        #pragma unroll
        for (int j2 = 0; j2 < 8; j2++) { ss += red[j2 * 33 + threadIdx.x]; ss2 += red2[j2 * 33 + threadIdx.x]; }
        float mu = ss * (1.f / 128.f);
        float var = ss2 * (1.f / 128.f) - mu * mu;
        mu_s[threadIdx.x] = mu; rs_s[threadIdx.x] = rsqrtf(var + 1e-5f);
    }
    __syncthreads();
    float mu = mu_s[px], rs = rs_s[px];
    unsigned* xl = g_u + OFF_X1LN + (size_t)(p0 + px) * 64 + j * 8;
    #pragma unroll
    for (int ii = 0; ii < 8; ii++) {
        int c = j * 16 + 2 * ii;
        float a = (v[2 * ii] - mu) * rs * w2s[c] + b2s[c];
        float bb = (v[2 * ii + 1] - mu) * rs * w2s[c + 1] + b2s[c + 1];
        xl[ii] = pk(a, bb);
    }
}

// ---------------------------------------------------------------------------
// K6: depthwise 3x3 + exact GELU gate, column-sweep in h with register window.
// y_in packed bf16x2 [p][512] -> y_g packed bf16x2 [p][256].
// ---------------------------------------------------------------------------
__device__ __forceinline__ void dw_loadrow(
    const unsigned* __restrict__ yin, int b, int h, int w, int cp,
    float2* a, float2* bb)
{
    #pragma unroll
    for (int dw = 0; dw < 3; dw++) { a[dw] = make_float2(0.f, 0.f); bb[dw] = make_float2(0.f, 0.f); }
    if (h < 0 || h >= 176) return;
    #pragma unroll
    for (int dw = 0; dw < 3; dw++) {
        int ww = w + dw - 1;
        if (ww < 0 || ww >= 176) continue;
        size_t base = ((size_t)b * HW + (size_t)h * 176 + ww) * 512;
        a[dw]  = bf2f(yin[base + cp]);
        bb[dw] = bf2f(yin[base + 256 + cp]);
    }
}

__global__ void __launch_bounds__(256) k_dwconv(const float* __restrict__ wdw)
{
    int gid = blockIdx.x * 256 + threadIdx.x;
    int cp = gid & 255;
    int r = gid >> 8;
    int w = r % 176, b = r / 176;
    const unsigned* yin = g_u + OFF_YIN;
    unsigned* yg = g_u + OFF_YG;
    int c0 = 2 * cp;
    float wa0[9], wa1[9], wb0[9], wb1[9];
    #pragma unroll
    for (int t = 0; t < 9; t++) {
        wa0[t] = __ldg(&wdw[c0 * 9 + t]);
        wa1[t] = __ldg(&wdw[(c0 + 1) * 9 + t]);
        wb0[t] = __ldg(&wdw[(512 + c0) * 9 + t]);
        wb1[t] = __ldg(&wdw[(513 + c0) * 9 + t]);
    }
    float2 A[3][3], B2[3][3];
    dw_loadrow(yin, b, -1, w, cp, A[0], B2[0]);
    dw_loadrow(yin, b, 0, w, cp, A[1], B2[1]);
    dw_loadrow(yin, b, 1, w, cp, A[2], B2[2]);

    for (int h = 0; h < 176; h++) {
        float a0 = 0.f, a1 = 0.f, g0 = 0.f, g1 = 0.f;
        #pragma unroll
        for (int rr = 0; rr < 3; rr++)
            #pragma unroll
            for (int cc = 0; cc < 3; cc++) {
                int t = rr * 3 + cc;
                a0 += A[rr][cc].x * wa0[t];
                a1 += A[rr][cc].y * wa1[t];
                g0 += B2[rr][cc].x * wb0[t];
                g1 += B2[rr][cc].y * wb1[t];
            }
        float e0 = 0.5f * a0 * (1.f + erff(a0 * 0.70710678118654752f));
        float e1 = 0.5f * a1 * (1.f + erff(a1 * 0.70710678118654752f));
        yg[((size_t)b * HW + (size_t)h * 176 + w) * 256 + cp] = pk(e0 * g0, e1 * g1);
        #pragma unroll
        for (int cc = 0; cc < 3; cc++) {
            A[0][cc] = A[1][cc]; A[1][cc] = A[2][cc];
            B2[0][cc] = B2[1][cc]; B2[1][cc] = B2[2][cc];
        }
        dw_loadrow(yin, b, h + 2, w, cp, A[2], B2[2]);
    }
}

// ---------------------------------------------------------------------------
// K7: conv_out bf16 MMA GEMM (KD=512) + residual -> final NCHW output.
// ---------------------------------------------------------------------------
__global__ void __launch_bounds__(256, 2) k_mma_out(float* __restrict__ outp)
{
    const int KP = 256, NST = 32;
    __shared__ unsigned Ap[2][8 * 136], Bp[2][8 * 136];
    const unsigned* Au = g_u + OFF_YG;
    const unsigned* Bu = g_u + OFF_WB + 90112;
    const float* x1 = (const float*)(g_u + OFF_X1);
    int m0 = blockIdx.x * 128;
    int b = m0 / HW, hw0 = m0 % HW;
    int tid = threadIdx.x, lane = tid & 31, warp = tid >> 5;
    int wm = warp >> 2, wn = warp & 3, t = lane & 3, g = lane >> 2;
    float acc[4][4][4];
    #pragma unroll
    for (int i = 0; i < 4; i++)
        #pragma unroll
        for (int j = 0; j < 4; j++)
            #pragma unroll
            for (int k = 0; k < 4; k++) acc[i][j][k] = 0.f;
    unsigned ra[4], rb[4];

    #pragma unroll
    for (int i = 0; i < 4; i++) {
        int idx = tid + i * 256; int kk = idx & 7, m = idx >> 3;
        ra[i] = Au[(size_t)(m0 + m) * KP + kk];
        rb[i] = Bu[(size_t)m * KP + kk];
    }
    #pragma unroll
    for (int i = 0; i < 4; i++) {
        int idx = tid + i * 256; int kk = idx & 7, m = idx >> 3;
        Ap[0][kk * 136 + m] = ra[i];
        Bp[0][kk * 136 + m] = rb[i];
    }
    __syncthreads();

    #pragma unroll 2
    for (int ks = 0; ks < NST; ks++) {
        int buf = ks & 1;
        if (ks + 1 < NST) {
            int kb = (ks + 1) * 8;
            #pragma unroll
            for (int i = 0; i < 4; i++) {
                int idx = tid + i * 256; int kk = idx & 7, m = idx >> 3;
                ra[i] = Au[(size_t)(m0 + m) * KP + kb + kk];
                rb[i] = Bu[(size_t)m * KP + kb + kk];
            }
        }
        mma_stage(Ap[buf], Bp[buf], acc, t, g, wm, wn);
        if (ks + 1 < NST) {
            #pragma unroll
            for (int i = 0; i < 4; i++) {
                int idx = tid + i * 256; int kk = idx & 7, m = idx >> 3;
                Ap[buf ^ 1][kk * 136 + m] = ra[i];
                Bp[buf ^ 1][kk * 136 + m] = rb[i];
            }
        }
        __syncthreads();
    }

    #pragma unroll
    for (int tm = 0; tm < 4; tm++)
        #pragma unroll
        for (int tn = 0; tn < 4; tn++) {
            int mrow = wm * 64 + tm * 16 + g;
            int n = wn * 32 + tn * 8 + 2 * t;
            size_t a0 = ((size_t)b * 128 + n) * HW + hw0 + mrow;
            outp[a0]          = x1[a0] + acc[tm][tn][0];
            outp[a0 + HW]     = x1[a0 + HW] + acc[tm][tn][1];
            outp[a0 + 8]      = x1[a0 + 8] + acc[tm][tn][2];
            outp[a0 + HW + 8] = x1[a0 + HW + 8] + acc[tm][tn][3];
        }
}

// ---------------------------------------------------------------------------
extern "C" void kernel_launch(void* const* d_in, const int* in_sizes, int n_in,
                              void* d_out, int out_size)
{
    const float* x    = (const float*)d_in[0];
    const float* mask = (const float*)d_in[1];
    const float* edge = (const float*)d_in[2];
    const float* ln1w = (const float*)d_in[3];
    const float* ln1b = (const float*)d_in[4];
    const float* Wq   = (const float*)d_in[5];
    const float* Wk   = (const float*)d_in[6];
    const float* Wv   = (const float*)d_in[7];
    const float* ln2w = (const float*)d_in[8];
    const float* ln2b = (const float*)d_in[9];
    const float* w_in = (const float*)d_in[10];
    const float* w_dw = (const float*)d_in[11];
    const float* w_out= (const float*)d_in[12];
    float* outp = (float*)d_out;

    unsigned* G = nullptr;
    cudaGetSymbolAddress((void**)&G, g_u);

    // K0: weights -> packed bf16x2
    k_wprep<<<(122880 + 255) / 256, 256>>>(Wq, Wk, Wv, w_in, w_out);

    // K1: LN1 + resize -> Aq/Akv packed
    k_prep<<<PTOT / 32, 256>>>(x, mask, edge, ln1w, ln1b);

    // K2: Q/K/V bf16 GEMMs (M=123904, N=128, K=128), fp32 C
    k_mma_g<128, 0><<<dim3(PTOT / 128, 1), 256>>>(G + OFF_AQ,  G + OFF_WB,         G + OFF_Q, 128);
    k_mma_g<128, 0><<<dim3(PTOT / 128, 1), 256>>>(G + OFF_AKV, G + OFF_WB + 8192,  G + OFF_K, 128);
    k_mma_g<128, 0><<<dim3(PTOT / 128, 1), 256>>>(G + OFF_AKV, G + OFF_WB + 16384, G + OFF_V, 128);

    // K3: channel attention -> AO (merged layout)
    k_attn<<<4 * 16 * 61, 256>>>();

    // K4: x1 = x + AO, LN2 applied & packed -> X1LN
    k_merge2<<<PTOT / 32, 256>>>(x, ln2w, ln2b);

    // K5: conv1x1 128->1024 bf16 GEMM -> y_in packed bf16
    k_mma_g<128, 1><<<dim3(PTOT / 128, 8), 256>>>(G + OFF_X1LN, G + OFF_WB + 24576, G + OFF_YIN, 1024);

    // K6: depthwise 3x3 + GELU gate -> y_g packed bf16
    k_dwconv<<<BATCH * 176, 256>>>(w_dw);

    // K7: conv1x1 512->128 + residual -> d_out (NCHW)
    k_mma_out<<<dim3(PTOT / 128, 1), 256>>>(outp);
}